// round 1
// baseline (speedup 1.0000x reference)
#include <cuda_runtime.h>
#include <math.h>

#define BODYD 10
#define FEATD 15
#define NOBJ  8
#define TB    8          // elements per block in k_main
#define PAIRS 64         // TB * NOBJ
#define XP    53         // x_sh pitch (pad for bank spread)
#define HP    261        // h_sh pitch (odd -> conflict-light)
#define WA1P  416        // padded N for a1 (400 -> 416, even 26-wide thread slices)
#define KC    8          // K-chunk for W_a1 streaming
#define UNION_FL 13056   // union region floats (Wa0 12800 + ba0 256)

#define EP  64           // elements per block in k_head
#define AP  404          // ip tile pitch
#define PPITCH 260       // p tile pitch

typedef unsigned long long ull;

// 104.9 MB scratch for input_pi (B x 400 fp32)
__device__ float g_ip[65536 * 400];

__device__ __forceinline__ ull packdup(float v) {
    ull r; asm("mov.b64 %0, {%1,%1};" : "=l"(r) : "f"(v)); return r;
}
__device__ __forceinline__ void unpack2(ull v, float& lo, float& hi) {
    asm("mov.b64 {%0,%1}, %2;" : "=f"(lo), "=f"(hi) : "l"(v));
}
#define FMA2(d, a, b) asm("fma.rn.f32x2 %0, %1, %2, %0;" : "+l"(d) : "l"(a), "l"(b))

// ---------------------------------------------------------------------------
// Kernel 1: attention + gather + a0 + a1 + object-sum -> g_ip (B x 400)
// Block = 8 elements = 64 (elem, obj) pairs, 256 threads.
// ---------------------------------------------------------------------------
__global__ __launch_bounds__(256, 1) void k_main(
    const float* __restrict__ o,   const float* __restrict__ g,
    const float* __restrict__ Wc,  const float* __restrict__ bc,
    const float* __restrict__ Wa0, const float* __restrict__ ba0,
    const float* __restrict__ Wa1, const float* __restrict__ ba1)
{
    extern __shared__ float sm[];
    float* x_sh = sm;                    // 64 x 53   = 3392
    float* h_sh = sm + PAIRS * XP;       // 64 x 261  = 16704
    float* u    = h_sh + PAIRS * HP;     // union     = 13056

    const int tid = threadIdx.x;
    const int e0  = blockIdx.x * TB;

    // ---------------- phase 0: attention + build scaled x ----------------
    {
        float* Wc_sh = u;            // 100 x 50 = 5000
        float* g_sh  = u + 5000;     // 8 x 100  = 800
        float* att   = u + 5800;     // 8 x 52   = 416
        for (int i = tid; i < 5000; i += 256) Wc_sh[i] = Wc[i];
        for (int i = tid; i < TB * 100; i += 256) g_sh[i] = g[(size_t)e0 * 100 + i];
        __syncthreads();

        for (int idx = tid; idx < TB * 50; idx += 256) {
            int e = idx / 50, j = idx % 50;
            float acc = bc[j];
            #pragma unroll 4
            for (int k = 0; k < 100; k++)
                acc = fmaf(g_sh[e * 100 + k], Wc_sh[k * 50 + j], acc);
            att[e * 52 + j] = 1.0f / (1.0f + expf(-acc));
        }
        __syncthreads();

        // x[e][n][d], d<20: body (o[0:10] ++ o[130:140]); d>=20: object slices
        for (int idx = tid; idx < TB * NOBJ * 50; idx += 256) {
            int e = idx / 400, r = idx % 400, n = r / 50, d = r % 50;
            int gi;
            if (d < 10)       gi = d;
            else if (d < 20)  gi = 120 + d;                 // 130 + (d-10)
            else if (d < 35)  gi = 15 * n + d - 10;         // 10 + 15n + (d-20)
            else              gi = 15 * n + d + 105;        // 140 + 15n + (d-35)
            x_sh[(e * NOBJ + n) * XP + d] =
                o[(size_t)(e0 + e) * 260 + gi] * att[e * 52 + d];
        }
        __syncthreads();
    }

    // ---------------- phase 1: h = relu(x @ Wa0 + ba0) ----------------
    {
        float* Wa0_sh = u;            // 50 x 256 = 12800
        float* ba0_sh = u + 12800;    // 256
        for (int i = tid; i < 12800; i += 256) Wa0_sh[i] = Wa0[i];
        if (tid < 256) ba0_sh[tid] = ba0[tid];
        __syncthreads();

        const int tx = tid & 15;   // pair group: pairs tx*4 .. tx*4+3
        const int ty = tid >> 4;   // j group:    j = ty*16 + 2i (+1)
        ull acc[4][8];
        #pragma unroll
        for (int p = 0; p < 4; p++)
            #pragma unroll
            for (int i = 0; i < 8; i++) acc[p][i] = 0ULL;

        for (int k = 0; k < 50; k++) {
            ull a[4];
            #pragma unroll
            for (int p = 0; p < 4; p++)
                a[p] = packdup(x_sh[(tx * 4 + p) * XP + k]);
            #pragma unroll
            for (int i = 0; i < 8; i++) {
                ull b = *(const ull*)&Wa0_sh[k * 256 + ty * 16 + 2 * i];
                FMA2(acc[0][i], a[0], b);
                FMA2(acc[1][i], a[1], b);
                FMA2(acc[2][i], a[2], b);
                FMA2(acc[3][i], a[3], b);
            }
        }
        #pragma unroll
        for (int p = 0; p < 4; p++)
            #pragma unroll
            for (int i = 0; i < 8; i++) {
                int j = ty * 16 + 2 * i;
                float lo, hi; unpack2(acc[p][i], lo, hi);
                h_sh[(tx * 4 + p) * HP + j]     = fmaxf(lo + ba0_sh[j],     0.f);
                h_sh[(tx * 4 + p) * HP + j + 1] = fmaxf(hi + ba0_sh[j + 1], 0.f);
            }
        __syncthreads();
    }

    // ------- phase 2: input_pi = sum_n relu(h @ Wa1 + ba1) -> g_ip -------
    {
        float* wbuf   = u;                    // KC x 416 = 3328
        float* ba1_sh = u + KC * WA1P;        // 416
        float* part   = ba1_sh + WA1P;        // 16 x 416 = 6656
        for (int i = tid; i < WA1P; i += 256) ba1_sh[i] = (i < 400) ? ba1[i] : 0.f;

        const int tx = tid & 15;   // j slice: j = tx*26 + 2i (+1)
        const int ty = tid >> 4;   // pair group: pairs ty*4 .. ty*4+3 (one e)
        ull acc[4][13];
        #pragma unroll
        for (int p = 0; p < 4; p++)
            #pragma unroll
            for (int i = 0; i < 13; i++) acc[p][i] = 0ULL;

        for (int k0 = 0; k0 < 256; k0 += KC) {
            for (int i = tid; i < KC * 400; i += 256)
                wbuf[(i / 400) * WA1P + (i % 400)] = Wa1[(size_t)k0 * 400 + i];
            for (int i = tid; i < KC * 16; i += 256)
                wbuf[(i / 16) * WA1P + 400 + (i % 16)] = 0.f;
            __syncthreads();
            #pragma unroll
            for (int kk = 0; kk < KC; kk++) {
                ull a[4];
                #pragma unroll
                for (int p = 0; p < 4; p++)
                    a[p] = packdup(h_sh[(ty * 4 + p) * HP + k0 + kk]);
                #pragma unroll
                for (int i = 0; i < 13; i++) {
                    ull b = *(const ull*)&wbuf[kk * WA1P + tx * 26 + 2 * i];
                    FMA2(acc[0][i], a[0], b);
                    FMA2(acc[1][i], a[1], b);
                    FMA2(acc[2][i], a[2], b);
                    FMA2(acc[3][i], a[3], b);
                }
            }
            __syncthreads();
        }

        // relu + partial sum over this thread's 4 objects (all same element)
        #pragma unroll
        for (int i = 0; i < 13; i++) {
            int j = tx * 26 + 2 * i;
            if (j < 400) {
                float s0 = 0.f, s1 = 0.f;
                #pragma unroll
                for (int p = 0; p < 4; p++) {
                    float lo, hi; unpack2(acc[p][i], lo, hi);
                    s0 += fmaxf(lo + ba1_sh[j],     0.f);
                    s1 += fmaxf(hi + ba1_sh[j + 1], 0.f);
                }
                part[ty * WA1P + j]     = s0;
                part[ty * WA1P + j + 1] = s1;
            }
        }
        __syncthreads();
        for (int idx = tid; idx < TB * 400; idx += 256) {
            int e = idx / 400, j = idx % 400;
            g_ip[(size_t)(e0 + e) * 400 + j] =
                part[(2 * e) * WA1P + j] + part[(2 * e + 1) * WA1P + j];
        }
    }
}

// ---------------------------------------------------------------------------
// Kernel 2: policy head  p0(relu) -> p1(relu) -> p2(tanh) -> out (B x 8)
// Block = 64 elements, 256 threads.
// ---------------------------------------------------------------------------
__global__ __launch_bounds__(256, 1) void k_head(
    const float* __restrict__ Wp0, const float* __restrict__ bp0,
    const float* __restrict__ Wp1, const float* __restrict__ bp1,
    const float* __restrict__ Wp2, const float* __restrict__ bp2,
    float* __restrict__ out)
{
    extern __shared__ float sm[];
    float* a_sh = sm;                      // 64 x 404 = 25856 (ip tile, later q)
    float* p_sh = a_sh + EP * AP;          // 64 x 260 = 16640
    float* wbuf = p_sh + EP * PPITCH;      // 16 x 256 = 4096
    float* w2   = wbuf + 16 * 256;         // 256 x 8  = 2048

    const int tid = threadIdx.x;
    const int e0  = blockIdx.x * EP;
    for (int i = tid; i < EP * 400; i += 256)
        a_sh[(i / 400) * AP + (i % 400)] = g_ip[(size_t)e0 * 400 + i];
    for (int i = tid; i < 2048; i += 256) w2[i] = Wp2[i];
    __syncthreads();

    const int tx = tid & 15;   // j pairs at tx*2 + 32i
    const int ty = tid >> 4;   // elements ty*4 .. ty*4+3

    // GEMM1: p = relu(ip @ Wp0 + bp0), K=400, N=256
    {
        ull acc[4][8];
        #pragma unroll
        for (int p = 0; p < 4; p++)
            #pragma unroll
            for (int i = 0; i < 8; i++) acc[p][i] = 0ULL;
        for (int k0 = 0; k0 < 400; k0 += 16) {
            for (int i = tid; i < 16 * 256; i += 256)
                wbuf[i] = Wp0[(size_t)k0 * 256 + i];
            __syncthreads();
            #pragma unroll
            for (int kk = 0; kk < 16; kk++) {
                ull a[4];
                #pragma unroll
                for (int p = 0; p < 4; p++)
                    a[p] = packdup(a_sh[(ty * 4 + p) * AP + k0 + kk]);
                #pragma unroll
                for (int i = 0; i < 8; i++) {
                    ull b = *(const ull*)&wbuf[kk * 256 + tx * 2 + 32 * i];
                    FMA2(acc[0][i], a[0], b);
                    FMA2(acc[1][i], a[1], b);
                    FMA2(acc[2][i], a[2], b);
                    FMA2(acc[3][i], a[3], b);
                }
            }
            __syncthreads();
        }
        #pragma unroll
        for (int p = 0; p < 4; p++)
            #pragma unroll
            for (int i = 0; i < 8; i++) {
                int j = tx * 2 + 32 * i;
                float lo, hi; unpack2(acc[p][i], lo, hi);
                p_sh[(ty * 4 + p) * PPITCH + j]     = fmaxf(lo + __ldg(bp0 + j),     0.f);
                p_sh[(ty * 4 + p) * PPITCH + j + 1] = fmaxf(hi + __ldg(bp0 + j + 1), 0.f);
            }
        __syncthreads();
    }

    // GEMM2: q = relu(p @ Wp1 + bp1), K=256, N=256 (q overwrites a_sh)
    {
        ull acc[4][8];
        #pragma unroll
        for (int p = 0; p < 4; p++)
            #pragma unroll
            for (int i = 0; i < 8; i++) acc[p][i] = 0ULL;
        for (int k0 = 0; k0 < 256; k0 += 16) {
            for (int i = tid; i < 16 * 256; i += 256)
                wbuf[i] = Wp1[(size_t)k0 * 256 + i];
            __syncthreads();
            #pragma unroll
            for (int kk = 0; kk < 16; kk++) {
                ull a[4];
                #pragma unroll
                for (int p = 0; p < 4; p++)
                    a[p] = packdup(p_sh[(ty * 4 + p) * PPITCH + k0 + kk]);
                #pragma unroll
                for (int i = 0; i < 8; i++) {
                    ull b = *(const ull*)&wbuf[kk * 256 + tx * 2 + 32 * i];
                    FMA2(acc[0][i], a[0], b);
                    FMA2(acc[1][i], a[1], b);
                    FMA2(acc[2][i], a[2], b);
                    FMA2(acc[3][i], a[3], b);
                }
            }
            __syncthreads();
        }
        #pragma unroll
        for (int p = 0; p < 4; p++)
            #pragma unroll
            for (int i = 0; i < 8; i++) {
                int j = tx * 2 + 32 * i;
                float lo, hi; unpack2(acc[p][i], lo, hi);
                a_sh[(ty * 4 + p) * PPITCH + j]     = fmaxf(lo + __ldg(bp1 + j),     0.f);
                a_sh[(ty * 4 + p) * PPITCH + j + 1] = fmaxf(hi + __ldg(bp1 + j + 1), 0.f);
            }
        __syncthreads();
    }

    // GEMM3: out = tanh(q @ Wp2 + bp2), N=8
    for (int idx = tid; idx < EP * 8; idx += 256) {
        int e = idx >> 3, jo = idx & 7;
        float acc = __ldg(bp2 + jo);
        #pragma unroll 8
        for (int k = 0; k < 256; k++)
            acc = fmaf(a_sh[e * PPITCH + k], w2[k * 8 + jo], acc);
        out[(size_t)(e0 + e) * 8 + jo] = tanhf(acc);
    }
}

// ---------------------------------------------------------------------------
extern "C" void kernel_launch(void* const* d_in, const int* in_sizes, int n_in,
                              void* d_out, int out_size)
{
    const float* o   = (const float*)d_in[0];
    const float* g   = (const float*)d_in[1];
    const float* Wc  = (const float*)d_in[2];
    const float* bc  = (const float*)d_in[3];
    const float* Wa0 = (const float*)d_in[4];
    const float* ba0 = (const float*)d_in[5];
    const float* Wa1 = (const float*)d_in[6];
    const float* ba1 = (const float*)d_in[7];
    const float* Wp0 = (const float*)d_in[8];
    const float* bp0 = (const float*)d_in[9];
    const float* Wp1 = (const float*)d_in[10];
    const float* bp1 = (const float*)d_in[11];
    const float* Wp2 = (const float*)d_in[12];
    const float* bp2 = (const float*)d_in[13];
    float* out = (float*)d_out;

    int B = in_sizes[0] / 260;

    size_t sm1 = (size_t)(PAIRS * XP + PAIRS * HP + UNION_FL) * sizeof(float);
    size_t sm3 = (size_t)(EP * AP + EP * PPITCH + 16 * 256 + 2048) * sizeof(float);
    cudaFuncSetAttribute(k_main, cudaFuncAttributeMaxDynamicSharedMemorySize, (int)sm1);
    cudaFuncSetAttribute(k_head, cudaFuncAttributeMaxDynamicSharedMemorySize, (int)sm3);

    k_main<<<B / TB, 256, sm1>>>(o, g, Wc, bc, Wa0, ba0, Wa1, ba1);
    k_head<<<B / EP, 256, sm3>>>(Wp0, bp0, Wp1, bp1, Wp2, bp2, out);
}